// round 14
// baseline (speedup 1.0000x reference)
#include <cuda_runtime.h>
#include <math.h>

// Problem constants (fixed shapes from reference setup_inputs)
#define B_      4
#define C_      256
#define P_      65536          // H*W = 256*256
#define NSEG    32             // object ids 1..32
#define PT      1024           // pixels per tile
#define TILES_PER_B (P_ / PT)  // 64
#define CH      128            // channels per block (tile split in 2)
#define NQH     (CH / 4)       // 32 channel-quads per block
#define NBLK1   (B_ * TILES_PER_B * 2)  // 512 pooling blocks (+1 wf block)
#define THREADS1 256

// Global segmented maxima as non-negative float bit-patterns: [b][seg][c], 128 KB.
// INVARIANT: zero at kernel_launch entry (zero at module load; epilogue re-zeros).
__device__ int g_gmax[B_ * NSEG * C_];
// Fused MLP weight Wf = w1@w2 [256][4] and bias = b2 + b1@w2 [4]
__device__ float g_wf[C_ * 4];
__device__ float g_bias[4];
// Arrival counter for the last-block-done barrier (reset by epilogue).
__device__ int g_counter;

// ---------------------------------------------------------------------------
// Single fused kernel (R13 pooling config + in-kernel epilogue):
//  - Blocks 0..NBLK1-1: per-(tile, channel-half) segmented max; accum
//    [cquad][id][4ch], LDS.128 snapshot + shared atomicMax on non-negative
//    float bits (stale-safe, monotone); 4+4 double-buffered loads; REDG.MAX
//    flush to g_gmax. 512 blocks -> ~3.5 CTAs/SM (~28 warps) at <=64 regs.
//  - Block NBLK1: computes Wf = w1@w2 and bias = b2 + b1@w2 (hidden in wave).
//  - All blocks fence + ticket. The 513th arrival runs the MLP epilogue
//    (Wf staged via shared), then re-zeros g_gmax and resets g_counter.
// ---------------------------------------------------------------------------
__global__ __launch_bounds__(THREADS1, 4)
void fused_kernel(const float* __restrict__ enc, const int* __restrict__ masks,
                  const float* __restrict__ w1, const float* __restrict__ b1,
                  const float* __restrict__ w2, const float* __restrict__ b2,
                  float* __restrict__ out) {
    __shared__ int4 accum4[NQH * 33];           // 16.9 KB
    __shared__ int s_ticket;
    int* accum = reinterpret_cast<int*>(accum4);

    const int blk  = blockIdx.x;
    const int tid  = threadIdx.x;
    const int warp = tid >> 5;
    const int lane = tid & 31;

    if (blk == NBLK1) {
        // ---- fused-weight block: 8 warps cover 256 c-rows, 32 rows each ----
        for (int r = 0; r < 32; r++) {
            const int c = r * 8 + warp;
            float a0 = 0.f, a1 = 0.f, a2 = 0.f, a3 = 0.f;
            #pragma unroll
            for (int k = 0; k < 4; k++) {
                const int j = lane + 32 * k;
                const float a = w1[c * 128 + j];
                const float4 wr = *reinterpret_cast<const float4*>(w2 + j * 4);
                a0 = fmaf(a, wr.x, a0); a1 = fmaf(a, wr.y, a1);
                a2 = fmaf(a, wr.z, a2); a3 = fmaf(a, wr.w, a3);
            }
            #pragma unroll
            for (int d = 16; d >= 1; d >>= 1) {
                a0 += __shfl_xor_sync(0xffffffffu, a0, d);
                a1 += __shfl_xor_sync(0xffffffffu, a1, d);
                a2 += __shfl_xor_sync(0xffffffffu, a2, d);
                a3 += __shfl_xor_sync(0xffffffffu, a3, d);
            }
            if (lane == 0)
                *reinterpret_cast<float4*>(g_wf + c * 4) = make_float4(a0, a1, a2, a3);
        }
        if (warp == 0) {
            float s0 = 0.f, s1 = 0.f, s2 = 0.f, s3 = 0.f;
            #pragma unroll
            for (int k = 0; k < 4; k++) {
                const int j = lane + 32 * k;
                const float bv = b1[j];
                const float4 wr = *reinterpret_cast<const float4*>(w2 + j * 4);
                s0 = fmaf(bv, wr.x, s0); s1 = fmaf(bv, wr.y, s1);
                s2 = fmaf(bv, wr.z, s2); s3 = fmaf(bv, wr.w, s3);
            }
            #pragma unroll
            for (int d = 16; d >= 1; d >>= 1) {
                s0 += __shfl_xor_sync(0xffffffffu, s0, d);
                s1 += __shfl_xor_sync(0xffffffffu, s1, d);
                s2 += __shfl_xor_sync(0xffffffffu, s2, d);
                s3 += __shfl_xor_sync(0xffffffffu, s3, d);
            }
            if (lane == 0) {
                g_bias[0] = s0 + b2[0];
                g_bias[1] = s1 + b2[1];
                g_bias[2] = s2 + b2[2];
                g_bias[3] = s3 + b2[3];
            }
        }
    } else {
        // ---- pooling block: (batch, tile, channel-half) ----
        const int b    = blk / (TILES_PER_B * 2);
        const int rem  = blk % (TILES_PER_B * 2);
        const int tile = rem >> 1;
        const int half = rem & 1;                   // 0: ch 0..127, 1: 128..255
        const int choff = half * CH;

        #pragma unroll
        for (int i = tid; i < NQH * 33 * 4; i += THREADS1) accum[i] = 0;

        const int pbase = tile * PT;
        const int4 idv = reinterpret_cast<const int4*>(masks + (size_t)b * P_ + pbase)[tid];
        const int id0 = idv.x, id1 = idv.y, id2 = idv.z, id3 = idv.w;

        __syncthreads();

        const float* encb = enc + ((size_t)b * C_ + choff) * P_ + pbase;

        #define LOADV(DST, CBASE)                                                   \
            _Pragma("unroll")                                                       \
            for (int u = 0; u < 4; u++)                                             \
                DST[u] = reinterpret_cast<const float4*>(encb + (size_t)((CBASE) + u) * P_)[tid];

        #define CHECK_PIXEL(CQ, IDX, SRC, COMP)                                     \
        {                                                                           \
            const int4 cur = accum4[(CQ) * 33 + IDX];                               \
            const int base = ((CQ) * 33 + IDX) * 4; int a;                          \
            a = __float_as_int(SRC[0].COMP); if (a > cur.x) atomicMax(&accum[base+0], a); \
            a = __float_as_int(SRC[1].COMP); if (a > cur.y) atomicMax(&accum[base+1], a); \
            a = __float_as_int(SRC[2].COMP); if (a > cur.z) atomicMax(&accum[base+2], a); \
            a = __float_as_int(SRC[3].COMP); if (a > cur.w) atomicMax(&accum[base+3], a); \
        }

        #define PROCESS(SRC, CBASE)                                                 \
        {                                                                           \
            const int cq = (CBASE) >> 2;                                            \
            CHECK_PIXEL(cq, id0, SRC, x)                                            \
            CHECK_PIXEL(cq, id1, SRC, y)                                            \
            CHECK_PIXEL(cq, id2, SRC, z)                                            \
            CHECK_PIXEL(cq, id3, SRC, w)                                            \
        }

        float4 va[4], vb[4];
        LOADV(va, 0)
        #pragma unroll 1
        for (int c0 = 0; c0 < CH; c0 += 8) {
            LOADV(vb, c0 + 4)
            PROCESS(va, c0)
            if (c0 + 8 < CH) { LOADV(va, c0 + 8) }
            PROCESS(vb, c0 + 4)
        }
        #undef LOADV
        #undef PROCESS
        #undef CHECK_PIXEL

        __syncthreads();

        // flush this half's channels to global maxima (drop id 0); REDG.MAX.
        #pragma unroll
        for (int i = tid; i < NSEG * CH; i += THREADS1) {
            const int s  = i >> 7;       // 0..31
            const int cl = i & 127;      // local channel 0..127
            atomicMax(&g_gmax[(b * NSEG + s) * C_ + choff + cl],
                      accum[((cl >> 2) * 33 + s + 1) * 4 + (cl & 3)]);
        }
    }

    // ---- arrival: last block (ticket == NBLK1, i.e. 513th) runs the epilogue ----
    __threadfence();
    __syncthreads();
    if (tid == 0) s_ticket = atomicAdd(&g_counter, 1);
    __syncthreads();
    if (s_ticket != NBLK1) return;

    __threadfence();   // acquire: all other blocks' REDG + wf stores visible

    // stage Wf (4 KB) into shared, reusing the accumulator space
    float4* s_wf = reinterpret_cast<float4*>(accum4);   // s_wf[c] = Wf row c
    #pragma unroll
    for (int i = tid; i < C_; i += THREADS1)
        s_wf[i] = make_float4(__ldcg(&g_wf[i * 4 + 0]), __ldcg(&g_wf[i * 4 + 1]),
                              __ldcg(&g_wf[i * 4 + 2]), __ldcg(&g_wf[i * 4 + 3]));
    __syncthreads();
    const float bias0 = __ldcg(&g_bias[0]), bias1 = __ldcg(&g_bias[1]),
                bias2 = __ldcg(&g_bias[2]), bias3 = __ldcg(&g_bias[3]);

    // warp w handles (b,seg) rows w*16 .. w*16+15
    for (int i = 0; i < 16; i++) {
        const int bn = warp * 16 + i;
        const int4* row = reinterpret_cast<const int4*>(g_gmax + bn * C_);
        const int4 ga = __ldcg(row + lane);        // c = lane*4 + j
        const int4 gb = __ldcg(row + 32 + lane);   // c = 128 + lane*4 + j

        float a0 = 0.f, a1 = 0.f, a2 = 0.f, a3 = 0.f;
        #define ACCUM(VAL, CC)                                                   \
        {                                                                        \
            const float v = __int_as_float(VAL);                                 \
            const float4 w = s_wf[CC];                                           \
            a0 = fmaf(v, w.x, a0); a1 = fmaf(v, w.y, a1);                        \
            a2 = fmaf(v, w.z, a2); a3 = fmaf(v, w.w, a3);                        \
        }
        ACCUM(ga.x, lane * 4 + 0) ACCUM(ga.y, lane * 4 + 1)
        ACCUM(ga.z, lane * 4 + 2) ACCUM(ga.w, lane * 4 + 3)
        ACCUM(gb.x, 128 + lane * 4 + 0) ACCUM(gb.y, 128 + lane * 4 + 1)
        ACCUM(gb.z, 128 + lane * 4 + 2) ACCUM(gb.w, 128 + lane * 4 + 3)
        #undef ACCUM

        #pragma unroll
        for (int d = 16; d >= 1; d >>= 1) {
            a0 += __shfl_xor_sync(0xffffffffu, a0, d);
            a1 += __shfl_xor_sync(0xffffffffu, a1, d);
            a2 += __shfl_xor_sync(0xffffffffu, a2, d);
            a3 += __shfl_xor_sync(0xffffffffu, a3, d);
        }
        if (lane == 0) {
            out[bn * 4 + 0] = 1.0f / (1.0f + expf(-(a0 + bias0)));
            out[bn * 4 + 1] = 1.0f / (1.0f + expf(-(a1 + bias1)));
            out[bn * 4 + 2] = 1.0f / (1.0f + expf(-(a2 + bias2)));
            out[bn * 4 + 3] = 1.0f / (1.0f + expf(-(a3 + bias3)));
        }
    }

    // restore zero invariant: each warp zeroes the rows it consumed
    const int4 z4 = make_int4(0, 0, 0, 0);
    for (int i = 0; i < 16; i++) {
        int4* row = reinterpret_cast<int4*>(g_gmax + (warp * 16 + i) * C_);
        row[lane]      = z4;
        row[32 + lane] = z4;
    }
    if (tid == 0) g_counter = 0;   // all arrivals already counted
}

// ---------------------------------------------------------------------------
extern "C" void kernel_launch(void* const* d_in, const int* in_sizes, int n_in,
                              void* d_out, int out_size) {
    const float* enc   = (const float*)d_in[0];  // [4,256,256,256] f32
    const float* w1    = (const float*)d_in[1];  // [256,128]
    const float* b1    = (const float*)d_in[2];  // [128]
    const float* w2    = (const float*)d_in[3];  // [128,4]
    const float* b2    = (const float*)d_in[4];  // [4]
    const int*   masks = (const int*)d_in[5];    // [4,1,256,256] i32

    fused_kernel<<<NBLK1 + 1, THREADS1>>>(enc, masks, w1, b1, w2, b2, (float*)d_out);
}

// round 15
// speedup vs baseline: 1.3186x; 1.3186x over previous
#include <cuda_runtime.h>
#include <math.h>

// Problem constants (fixed shapes from reference setup_inputs)
#define B_      4
#define C_      256
#define P_      65536          // H*W = 256*256
#define NSEG    32             // object ids 1..32
#define PT      1024           // pixels per tile
#define TILES_PER_B (P_ / PT)  // 64
#define CH      128            // channels per block (tile split in 2)
#define NQH     (CH / 4)       // 32 channel-quads per block
#define NBLK1   (B_ * TILES_PER_B * 2)  // 512 pooling blocks (+1 wf block)
#define THREADS1 256

// Global segmented maxima as non-negative float bit-patterns: [b][seg][c], 128 KB.
// INVARIANT: zero at kernel_launch entry (zero-initialized at module load;
// mlp_kernel re-zeros after consuming, so every call/replay sees zeros).
__device__ int g_gmax[B_ * NSEG * C_];
// Fused MLP weight Wf = w1@w2 [256][4] and bias = b2 + b1@w2 [4]
__device__ float g_wf[C_ * 4];
__device__ float g_bias[4];

// ---------------------------------------------------------------------------
// Phase 1: per-(tile, channel-half) segmented max. accum [cquad][id][4ch];
// one LDS.128 snapshots 4 channels' maxima for a pixel's id. Non-negative
// float bits (init 0 == clamp at 0; int cmp == float cmp); stale snapshots
// safe (monotone). 4+4 double-buffered loads; 512 blocks -> ~3.5 CTAs/SM.
// Flush: fire-and-forget REDG.MAX straight to g_gmax — NO fence, NO barrier;
// block exit + kernel boundary handle the drain (the in-kernel fence variant
// measured +20us in R14).
// The LAST block computes Wf = w1@w2 and bias = b2 + b1@w2 instead.
// ---------------------------------------------------------------------------
__global__ __launch_bounds__(THREADS1, 4)
void seg_pool_kernel(const float* __restrict__ enc, const int* __restrict__ masks,
                     const float* __restrict__ w1, const float* __restrict__ b1,
                     const float* __restrict__ w2, const float* __restrict__ b2) {
    const int blk  = blockIdx.x;
    const int tid  = threadIdx.x;
    const int warp = tid >> 5;
    const int lane = tid & 31;

    if (blk == NBLK1) {
        // ---- fused-weight block: 8 warps cover 256 c-rows, 32 rows each ----
        for (int r = 0; r < 32; r++) {
            const int c = r * 8 + warp;
            float a0 = 0.f, a1 = 0.f, a2 = 0.f, a3 = 0.f;
            #pragma unroll
            for (int k = 0; k < 4; k++) {
                const int j = lane + 32 * k;
                const float a = w1[c * 128 + j];
                const float4 wr = *reinterpret_cast<const float4*>(w2 + j * 4);
                a0 = fmaf(a, wr.x, a0); a1 = fmaf(a, wr.y, a1);
                a2 = fmaf(a, wr.z, a2); a3 = fmaf(a, wr.w, a3);
            }
            #pragma unroll
            for (int d = 16; d >= 1; d >>= 1) {
                a0 += __shfl_xor_sync(0xffffffffu, a0, d);
                a1 += __shfl_xor_sync(0xffffffffu, a1, d);
                a2 += __shfl_xor_sync(0xffffffffu, a2, d);
                a3 += __shfl_xor_sync(0xffffffffu, a3, d);
            }
            if (lane == 0)
                *reinterpret_cast<float4*>(g_wf + c * 4) = make_float4(a0, a1, a2, a3);
        }
        if (warp == 0) {
            float s0 = 0.f, s1 = 0.f, s2 = 0.f, s3 = 0.f;
            #pragma unroll
            for (int k = 0; k < 4; k++) {
                const int j = lane + 32 * k;
                const float bv = b1[j];
                const float4 wr = *reinterpret_cast<const float4*>(w2 + j * 4);
                s0 = fmaf(bv, wr.x, s0); s1 = fmaf(bv, wr.y, s1);
                s2 = fmaf(bv, wr.z, s2); s3 = fmaf(bv, wr.w, s3);
            }
            #pragma unroll
            for (int d = 16; d >= 1; d >>= 1) {
                s0 += __shfl_xor_sync(0xffffffffu, s0, d);
                s1 += __shfl_xor_sync(0xffffffffu, s1, d);
                s2 += __shfl_xor_sync(0xffffffffu, s2, d);
                s3 += __shfl_xor_sync(0xffffffffu, s3, d);
            }
            if (lane == 0) {
                g_bias[0] = s0 + b2[0];
                g_bias[1] = s1 + b2[1];
                g_bias[2] = s2 + b2[2];
                g_bias[3] = s3 + b2[3];
            }
        }
        return;
    }

    __shared__ int4 accum4[NQH * 33];           // 16.9 KB
    int* accum = reinterpret_cast<int*>(accum4);

    // block -> (batch, tile, channel-half)
    const int b    = blk / (TILES_PER_B * 2);
    const int rem  = blk % (TILES_PER_B * 2);
    const int tile = rem >> 1;
    const int half = rem & 1;                   // 0: ch 0..127, 1: 128..255
    const int choff = half * CH;

    #pragma unroll
    for (int i = tid; i < NQH * 33 * 4; i += THREADS1) accum[i] = 0;

    const int pbase = tile * PT;
    const int4 idv = reinterpret_cast<const int4*>(masks + (size_t)b * P_ + pbase)[tid];
    const int id0 = idv.x, id1 = idv.y, id2 = idv.z, id3 = idv.w;

    __syncthreads();

    const float* encb = enc + ((size_t)b * C_ + choff) * P_ + pbase;

    #define LOADV(DST, CBASE)                                                   \
        _Pragma("unroll")                                                       \
        for (int u = 0; u < 4; u++)                                             \
            DST[u] = reinterpret_cast<const float4*>(encb + (size_t)((CBASE) + u) * P_)[tid];

    // one channel-quad (4 consecutive channels), 4 pixels per thread
    #define CHECK_PIXEL(CQ, IDX, SRC, COMP)                                     \
    {                                                                           \
        const int4 cur = accum4[(CQ) * 33 + IDX];                               \
        const int base = ((CQ) * 33 + IDX) * 4; int a;                          \
        a = __float_as_int(SRC[0].COMP); if (a > cur.x) atomicMax(&accum[base+0], a); \
        a = __float_as_int(SRC[1].COMP); if (a > cur.y) atomicMax(&accum[base+1], a); \
        a = __float_as_int(SRC[2].COMP); if (a > cur.z) atomicMax(&accum[base+2], a); \
        a = __float_as_int(SRC[3].COMP); if (a > cur.w) atomicMax(&accum[base+3], a); \
    }

    #define PROCESS(SRC, CBASE)                                                 \
    {                                                                           \
        const int cq = (CBASE) >> 2;                                            \
        CHECK_PIXEL(cq, id0, SRC, x)                                            \
        CHECK_PIXEL(cq, id1, SRC, y)                                            \
        CHECK_PIXEL(cq, id2, SRC, z)                                            \
        CHECK_PIXEL(cq, id3, SRC, w)                                            \
    }

    float4 va[4], vb[4];
    LOADV(va, 0)
    #pragma unroll 1
    for (int c0 = 0; c0 < CH; c0 += 8) {
        LOADV(vb, c0 + 4)
        PROCESS(va, c0)
        if (c0 + 8 < CH) { LOADV(va, c0 + 8) }
        PROCESS(vb, c0 + 4)
    }
    #undef LOADV
    #undef PROCESS
    #undef CHECK_PIXEL

    __syncthreads();

    // flush this half's channels straight to global maxima (drop id 0);
    // fire-and-forget REDG.MAX — no round trip, no fence.
    #pragma unroll
    for (int i = tid; i < NSEG * CH; i += THREADS1) {
        const int s  = i >> 7;       // 0..31
        const int cl = i & 127;      // local channel 0..127
        atomicMax(&g_gmax[(b * NSEG + s) * C_ + choff + cl],
                  accum[((cl >> 2) * 33 + s + 1) * 4 + (cl & 3)]);
    }
}

// ---------------------------------------------------------------------------
// Phase 2: read the 128 KB global maxima (L2-hot), multiply by the fused
// weight, 4-warp tree sum, sigmoid. One block per (b,seg). Each block then
// RE-ZEROS its own g_gmax slice (after a barrier), restoring the entry
// invariant for the next call/replay.
// ---------------------------------------------------------------------------
__global__ __launch_bounds__(1024)
void mlp_kernel(float* __restrict__ out) {
    __shared__ float mlp[4][C_];     // 4 KB

    const int blk = blockIdx.x;      // b*NSEG + n
    const int tid = threadIdx.x;
    const int c   = tid >> 2;        // 0..255
    const int o   = tid & 3;         // 0..3

    const float val = __int_as_float(g_gmax[blk * C_ + c]);  // >= 0 by construction
    mlp[o][c] = val * g_wf[tid];
    __syncthreads();                 // all reads of this block's slice done

    // restore the zero invariant (each block owns its own 256-int slice)
    if (tid < C_) g_gmax[blk * C_ + tid] = 0;

    const int wid = tid >> 5, lane = tid & 31;
    if (wid < 4) {
        float s = 0.0f;
        #pragma unroll
        for (int k = 0; k < 8; k++) s += mlp[wid][lane + 32 * k];
        #pragma unroll
        for (int d = 16; d >= 1; d >>= 1) s += __shfl_xor_sync(0xffffffffu, s, d);
        if (lane == 0)
            out[blk * 4 + wid] = 1.0f / (1.0f + expf(-(s + g_bias[wid])));
    }
}

// ---------------------------------------------------------------------------
extern "C" void kernel_launch(void* const* d_in, const int* in_sizes, int n_in,
                              void* d_out, int out_size) {
    const float* enc   = (const float*)d_in[0];  // [4,256,256,256] f32
    const float* w1    = (const float*)d_in[1];  // [256,128]
    const float* b1    = (const float*)d_in[2];  // [128]
    const float* w2    = (const float*)d_in[3];  // [128,4]
    const float* b2    = (const float*)d_in[4];  // [4]
    const int*   masks = (const int*)d_in[5];    // [4,1,256,256] i32

    seg_pool_kernel<<<NBLK1 + 1, THREADS1>>>(enc, masks, w1, b1, w2, b2);
    mlp_kernel<<<B_ * NSEG, 1024>>>((float*)d_out);
}